// round 1
// baseline (speedup 1.0000x reference)
#include <cuda_runtime.h>

#define B_   64
#define L_   1024
#define ENC_ 2048
#define DEC_ 512
#define ATT_ 512

// ---- scratch (no allocations allowed) ----
__device__ float g_att2[B_ * ATT_];            // att2 + b_enc + b_dec, (B, ATT)
__device__ float g_part[4 * B_ * L_];          // per-N-chunk partial logits (deterministic, no atomics)

// ============================================================
// Kernel 1: att2[b][a] = dec[b]·W_dec[:,a] + b_dec[a] + b_enc[a]
// grid(B_), block(512)
// ============================================================
__global__ void k_att2(const float* __restrict__ dec,
                       const float* __restrict__ Wd,
                       const float* __restrict__ bd,
                       const float* __restrict__ be) {
    __shared__ float s[DEC_];
    int b = blockIdx.x;
    int a = threadIdx.x;                       // 512 threads == ATT_
    for (int d = threadIdx.x; d < DEC_; d += blockDim.x)
        s[d] = dec[b * DEC_ + d];
    __syncthreads();
    float acc = bd[a] + be[a];
    #pragma unroll 8
    for (int d = 0; d < DEC_; d++)
        acc = fmaf(s[d], Wd[d * ATT_ + a], acc);
    g_att2[b * ATT_ + a] = acc;
}

// ============================================================
// Kernel 2: fused big GEMM + relu + weighted reduce
//   partial_logit[nb][m] = sum_{a in chunk nb} relu(enc[m]·W_enc[:,a] + att2[b][a]) * W_full[a]
// Block tile: BM=64 rows x BN=128 cols, BK=32. 256 threads, 8x4 microtile.
// grid(M/BM = 1024, 4)
// ============================================================
#define BM 64
#define BN 128
#define BK 32
#define APAD 68   // BM+4: keeps float4 alignment for LDS vectorization

__global__ __launch_bounds__(256) void k_logits(const float* __restrict__ enc,
                                                const float* __restrict__ We,
                                                const float* __restrict__ Wf) {
    __shared__ float As[BK * APAD];   // transposed: As[k][m]
    __shared__ float Bs[BK * BN];     // Bs[k][n]
    __shared__ float s_c[BN];         // att2 chunk
    __shared__ float s_w[BN];         // W_full chunk

    const int tid    = threadIdx.x;
    const int m_base = blockIdx.x * BM;           // global flattened row (b*L + l)
    const int nb     = blockIdx.y;                // 0..3
    const int nbase  = nb * BN;
    const int b      = m_base / L_;               // BM=64 divides L_, tile never crosses b

    if (tid < BN) {
        s_c[tid] = g_att2[b * ATT_ + nbase + tid];
        s_w[tid] = Wf[nbase + tid];
    }

    float acc[8][4];
    #pragma unroll
    for (int i = 0; i < 8; i++)
        #pragma unroll
        for (int j = 0; j < 4; j++) acc[i][j] = 0.f;

    const int ty = tid >> 5;        // 0..7  -> rows  m0 = ty*8
    const int tx = tid & 31;        // 0..31 -> cols  n0 = tx*4
    const int m0 = ty * 8;
    const int n0 = tx * 4;

    const float* Ab = enc + (size_t)m_base * ENC_;

    for (int k0 = 0; k0 < ENC_; k0 += BK) {
        // load A tile (64x32), store transposed As[k][m]; coalesced in k
        #pragma unroll
        for (int i = 0; i < 8; i++) {
            int lin = tid + i * 256;
            int m = lin >> 5;
            int k = lin & 31;
            As[k * APAD + m] = Ab[(size_t)m * ENC_ + k0 + k];
        }
        // load B tile (32x128); coalesced in n
        #pragma unroll
        for (int i = 0; i < 16; i++) {
            int lin = tid + i * 256;
            int k = lin >> 7;
            int n = lin & 127;
            Bs[k * BN + n] = We[(size_t)(k0 + k) * ATT_ + nbase + n];
        }
        __syncthreads();

        #pragma unroll
        for (int kk = 0; kk < BK; kk++) {
            float af[8], bf[4];
            #pragma unroll
            for (int i = 0; i < 8; i++) af[i] = As[kk * APAD + m0 + i];
            #pragma unroll
            for (int j = 0; j < 4; j++) bf[j] = Bs[kk * BN + n0 + j];
            #pragma unroll
            for (int i = 0; i < 8; i++)
                #pragma unroll
                for (int j = 0; j < 4; j++)
                    acc[i][j] = fmaf(af[i], bf[j], acc[i][j]);
        }
        __syncthreads();
    }

    // epilogue: relu(acc + att2) · w, reduce across the warp's 128 columns
    float part[8];
    #pragma unroll
    for (int i = 0; i < 8; i++) {
        float s = 0.f;
        #pragma unroll
        for (int j = 0; j < 4; j++) {
            float v = acc[i][j] + s_c[n0 + j];
            v = v > 0.f ? v : 0.f;
            s = fmaf(v, s_w[n0 + j], s);
        }
        part[i] = s;
    }
    #pragma unroll
    for (int off = 16; off; off >>= 1)
        #pragma unroll
        for (int i = 0; i < 8; i++)
            part[i] += __shfl_xor_sync(0xffffffffu, part[i], off);

    if (tx == 0) {
        float* dst = &g_part[nb * (B_ * L_) + m_base + m0];
        #pragma unroll
        for (int i = 0; i < 8; i++) dst[i] = part[i];
    }
}

// ============================================================
// Kernel 3: softmax over L per batch; writes att to output
// grid(B_), block(256)
// ============================================================
__global__ void k_softmax(float* __restrict__ out_att) {
    const int b   = blockIdx.x;
    const int tid = threadIdx.x;
    __shared__ float red[8];

    float v[4];
    #pragma unroll
    for (int i = 0; i < 4; i++) {
        int l = tid + i * 256;
        float s = 0.f;
        #pragma unroll
        for (int p = 0; p < 4; p++)
            s += g_part[p * (B_ * L_) + b * L_ + l];
        v[i] = s;
    }

    // block max
    float mx = fmaxf(fmaxf(v[0], v[1]), fmaxf(v[2], v[3]));
    #pragma unroll
    for (int off = 16; off; off >>= 1)
        mx = fmaxf(mx, __shfl_xor_sync(0xffffffffu, mx, off));
    if ((tid & 31) == 0) red[tid >> 5] = mx;
    __syncthreads();
    float bm = red[0];
    #pragma unroll
    for (int i = 1; i < 8; i++) bm = fmaxf(bm, red[i]);
    __syncthreads();

    // exp + block sum
    float sum = 0.f;
    #pragma unroll
    for (int i = 0; i < 4; i++) {
        v[i] = expf(v[i] - bm);
        sum += v[i];
    }
    #pragma unroll
    for (int off = 16; off; off >>= 1)
        sum += __shfl_xor_sync(0xffffffffu, sum, off);
    if ((tid & 31) == 0) red[tid >> 5] = sum;
    __syncthreads();
    float tot = 0.f;
    #pragma unroll
    for (int i = 0; i < 8; i++) tot += red[i];
    float inv = 1.f / tot;

    #pragma unroll
    for (int i = 0; i < 4; i++)
        out_att[b * L_ + tid + i * 256] = v[i] * inv;
}

// ============================================================
// Kernel 4: context[b][e] = sum_l att[b][l] * enc[b][l][e]
// grid(ENC_/256, B_), block(256)
// ============================================================
__global__ __launch_bounds__(256) void k_context(const float* __restrict__ enc,
                                                 const float* __restrict__ att,
                                                 float* __restrict__ ctx) {
    const int b = blockIdx.y;
    const int e = blockIdx.x * 256 + threadIdx.x;
    __shared__ float sa[L_];
    for (int l = threadIdx.x; l < L_; l += 256)
        sa[l] = att[b * L_ + l];
    __syncthreads();

    const float* ep = enc + (size_t)b * L_ * ENC_ + e;
    float acc = 0.f;
    #pragma unroll 8
    for (int l = 0; l < L_; l++)
        acc = fmaf(sa[l], ep[(size_t)l * ENC_], acc);
    ctx[b * ENC_ + e] = acc;
}

// ============================================================
extern "C" void kernel_launch(void* const* d_in, const int* in_sizes, int n_in,
                              void* d_out, int out_size) {
    const float* enc  = (const float*)d_in[0];  // (B, L, ENC)
    const float* dech = (const float*)d_in[1];  // (B, DEC)
    const float* We   = (const float*)d_in[2];  // (ENC, ATT)
    const float* be   = (const float*)d_in[3];  // (ATT)
    const float* Wd   = (const float*)d_in[4];  // (DEC, ATT)
    const float* bd   = (const float*)d_in[5];  // (ATT)
    const float* Wf   = (const float*)d_in[6];  // (ATT, 1)
    // d_in[7] = b_full: constant logit shift, invariant under softmax -> unused

    float* out_ctx = (float*)d_out;              // (B, ENC)
    float* out_att = (float*)d_out + B_ * ENC_;  // (B, L)

    k_att2<<<B_, 512>>>(dech, Wd, bd, be);
    dim3 g2(L_ * B_ / BM, ATT_ / BN);            // (1024, 4)
    k_logits<<<g2, 256>>>(enc, We, Wf);
    k_softmax<<<B_, 256>>>(out_att);
    dim3 g4(ENC_ / 256, B_);                     // (8, 64)
    k_context<<<g4, 256>>>(enc, out_att, out_ctx);
}

// round 3
// speedup vs baseline: 3.9468x; 3.9468x over previous
#include <cuda_runtime.h>
#include <cstdint>

#define B_   64
#define L_   1024
#define ENC_ 2048
#define DEC_ 512
#define ATT_ 512

// ---------------- scratch (no allocs allowed) ----------------
__device__ float g_att2[B_ * ATT_];            // att2 + b_enc + b_dec
__device__ float g_part[4 * B_ * L_];          // logit partials per N-chunk
__device__ float g_Wt[ATT_ * ENC_];            // W_enc^T (ATT, ENC), tf32-rounded
__device__ float g_ctxp[4 * B_ * ENC_];        // context partials (L-split)

// ============================================================
// Transpose W_enc (ENC,ATT) -> g_Wt (ATT,ENC), rounding to tf32 (rna)
// ============================================================
__global__ void k_transpose(const float* __restrict__ We) {
    __shared__ float t[32][33];
    const int k0 = blockIdx.x * 32, n0 = blockIdx.y * 32;
    const int tx = threadIdx.x, ty = threadIdx.y;  // (32, 8)
    #pragma unroll
    for (int j = 0; j < 4; j++) {
        float v = We[(size_t)(k0 + ty + j * 8) * ATT_ + n0 + tx];
        uint32_t r;
        asm("cvt.rna.tf32.f32 %0, %1;" : "=r"(r) : "f"(v));
        t[ty + j * 8][tx] = __uint_as_float(r);
    }
    __syncthreads();
    #pragma unroll
    for (int j = 0; j < 4; j++)
        g_Wt[(size_t)(n0 + ty + j * 8) * ENC_ + k0 + tx] = t[tx][ty + j * 8];
}

// ============================================================
// att2[b][a] = dec[b]·W_dec[:,a] + b_dec[a] + b_enc[a]
// ============================================================
__global__ void k_att2(const float* __restrict__ dec, const float* __restrict__ Wd,
                       const float* __restrict__ bd, const float* __restrict__ be) {
    __shared__ float s[DEC_];
    int b = blockIdx.x, a = threadIdx.x;
    for (int d = threadIdx.x; d < DEC_; d += blockDim.x) s[d] = dec[b * DEC_ + d];
    __syncthreads();
    float acc = bd[a] + be[a];
    #pragma unroll 8
    for (int d = 0; d < DEC_; d++) acc = fmaf(s[d], Wd[d * ATT_ + a], acc);
    g_att2[b * ATT_ + a] = acc;
}

// ============================================================
// Big GEMM via mma.sync tf32 + fused relu/dot epilogue
// CTA tile 128(M) x 128(N), BK=32 floats, 2-stage cp.async pipeline.
// 8 warps: warp_m = wid>>2 (2), warp_n = wid&3 (4); warp tile 64x32.
// grid(4 = N-chunk, 512 = M-block), block(256)
// ============================================================
#define BK       32
#define NITER    (ENC_ / BK)            // 64
#define A_STG    16384                  // 128 rows * 128B
#define B_STG    16384
#define STG      (A_STG + B_STG)        // 32768
#define SMEM_DYN (2 * STG)              // 65536

#define CP_ASYNC16(dst, src) \
    asm volatile("cp.async.cg.shared.global [%0], [%1], 16;" :: "r"(dst), "l"(src) : "memory")

__device__ __forceinline__ uint32_t smem_u32(const void* p) {
    uint32_t a;
    asm("{ .reg .u64 t; cvta.to.shared.u64 t, %1; cvt.u32.u64 %0, t; }" : "=r"(a) : "l"(p));
    return a;
}

__device__ __forceinline__ void mma_tf32(float* d, const uint32_t* a, const uint32_t* b) {
    asm volatile(
        "mma.sync.aligned.m16n8k8.row.col.f32.tf32.tf32.f32 "
        "{%0,%1,%2,%3}, {%4,%5,%6,%7}, {%8,%9}, {%0,%1,%2,%3};"
        : "+f"(d[0]), "+f"(d[1]), "+f"(d[2]), "+f"(d[3])
        : "r"(a[0]), "r"(a[1]), "r"(a[2]), "r"(a[3]), "r"(b[0]), "r"(b[1]));
}

__global__ __launch_bounds__(256) void k_logits_mma(const float* __restrict__ enc,
                                                    const float* __restrict__ Wf) {
    extern __shared__ char dsm[];
    __shared__ float s_c[128], s_w[128];
    __shared__ float ep[4][128];

    const int tid    = threadIdx.x;
    const int nb     = blockIdx.x;               // 0..3
    const int m_base = blockIdx.y * 128;
    const int n_base = nb * 128;
    const int b      = m_base / L_;

    const int wid    = tid >> 5;
    const int lane   = tid & 31;
    const int g      = lane >> 2;                // 0..7
    const int t4     = lane & 3;                 // 0..3
    const int warp_m = wid >> 2;                 // 0..1
    const int warp_n = wid & 3;                  // 0..3
    const int m0     = warp_m * 64;
    const int n0     = warp_n * 32;

    if (tid < 128) {
        s_c[tid] = g_att2[b * ATT_ + n_base + tid];
        s_w[tid] = Wf[n_base + tid];
    }

    const uint32_t smem = smem_u32(dsm);

    // ---- stage loader: 2048 16B chunks, 8 per thread ----
    auto load_stage = [&](int st, int k0f) {
        const uint32_t sb = smem + st * STG;
        #pragma unroll
        for (int it = 0; it < 8; it++) {
            int t = tid + it * 256;
            if (t < 1024) {
                int row = t >> 3, c = t & 7;
                const float* src = enc + (size_t)(m_base + row) * ENC_ + k0f + c * 4;
                CP_ASYNC16(sb + row * 128 + ((c ^ (row & 7)) << 4), src);
            } else {
                int u = t - 1024;
                int n = u >> 3, c = u & 7;
                const float* src = g_Wt + (size_t)(n_base + n) * ENC_ + k0f + c * 4;
                CP_ASYNC16(sb + A_STG + n * 128 + ((c ^ (n & 7)) << 4), src);
            }
        }
        asm volatile("cp.async.commit_group;" ::: "memory");
    };

    float acc[4][4][4];
    #pragma unroll
    for (int mi = 0; mi < 4; mi++)
        #pragma unroll
        for (int ni = 0; ni < 4; ni++)
            #pragma unroll
            for (int j = 0; j < 4; j++) acc[mi][ni][j] = 0.f;

    load_stage(0, 0);
    load_stage(1, BK);

    for (int i = 0; i < NITER; i++) {
        if (i < NITER - 1)
            asm volatile("cp.async.wait_group 1;" ::: "memory");
        else
            asm volatile("cp.async.wait_group 0;" ::: "memory");
        __syncthreads();

        const uint32_t sb = smem + (i & 1) * STG;
        const uint32_t Ab = sb + t4 * 4;
        const uint32_t Bb = sb + A_STG + t4 * 4;

        #pragma unroll
        for (int s = 0; s < 4; s++) {
            const uint32_t x0 = (uint32_t)((2 * s) ^ g) << 4;
            const uint32_t x1 = (uint32_t)((2 * s + 1) ^ g) << 4;

            uint32_t af[4][4], bf[4][2];
            #pragma unroll
            for (int mi = 0; mi < 4; mi++) {
                uint32_t r = Ab + (uint32_t)(m0 + mi * 16 + g) * 128;
                af[mi][0] = *(const uint32_t*)(dsm + (r + x0) - smem + (smem - smem));
                af[mi][0] = *(const uint32_t*)(dsm + (r - smem) + x0);
                af[mi][1] = *(const uint32_t*)(dsm + (r - smem) + 1024 + x0);
                af[mi][2] = *(const uint32_t*)(dsm + (r - smem) + x1);
                af[mi][3] = *(const uint32_t*)(dsm + (r - smem) + 1024 + x1);
            }
            #pragma unroll
            for (int ni = 0; ni < 4; ni++) {
                uint32_t r = Bb + (uint32_t)(n0 + ni * 8 + g) * 128;
                bf[ni][0] = *(const uint32_t*)(dsm + (r - smem) + x0);
                bf[ni][1] = *(const uint32_t*)(dsm + (r - smem) + x1);
            }
            #pragma unroll
            for (int mi = 0; mi < 4; mi++)
                #pragma unroll
                for (int ni = 0; ni < 4; ni++)
                    mma_tf32(acc[mi][ni], af[mi], bf[ni]);
        }
        __syncthreads();
        if (i + 2 < NITER) load_stage(i & 1, (i + 2) * BK);
    }

    // ---- epilogue: relu(acc + att2)·Wf, reduce over this CTA's 128 cols ----
    #pragma unroll
    for (int mi = 0; mi < 4; mi++) {
        float r0s = 0.f, r1s = 0.f;
        #pragma unroll
        for (int ni = 0; ni < 4; ni++) {
            int c = n0 + ni * 8 + 2 * t4;
            float v;
            v = acc[mi][ni][0] + s_c[c];     v = fmaxf(v, 0.f); r0s = fmaf(v, s_w[c], r0s);
            v = acc[mi][ni][1] + s_c[c + 1]; v = fmaxf(v, 0.f); r0s = fmaf(v, s_w[c + 1], r0s);
            v = acc[mi][ni][2] + s_c[c];     v = fmaxf(v, 0.f); r1s = fmaf(v, s_w[c], r1s);
            v = acc[mi][ni][3] + s_c[c + 1]; v = fmaxf(v, 0.f); r1s = fmaf(v, s_w[c + 1], r1s);
        }
        r0s += __shfl_xor_sync(0xffffffffu, r0s, 1);
        r0s += __shfl_xor_sync(0xffffffffu, r0s, 2);
        r1s += __shfl_xor_sync(0xffffffffu, r1s, 1);
        r1s += __shfl_xor_sync(0xffffffffu, r1s, 2);
        if (t4 == 0) {
            ep[warp_n][m0 + mi * 16 + g]     = r0s;
            ep[warp_n][m0 + mi * 16 + 8 + g] = r1s;
        }
    }
    __syncthreads();
    if (tid < 128) {
        float lg = ep[0][tid] + ep[1][tid] + ep[2][tid] + ep[3][tid];
        g_part[nb * (B_ * L_) + m_base + tid] = lg;
    }
}

// ============================================================
// softmax over L per batch (sums the 4 N-partials)
// ============================================================
__global__ void k_softmax(float* __restrict__ out_att) {
    const int b = blockIdx.x, tid = threadIdx.x;
    __shared__ float red[8];
    float v[4];
    #pragma unroll
    for (int i = 0; i < 4; i++) {
        int l = tid + i * 256;
        float s = 0.f;
        #pragma unroll
        for (int p = 0; p < 4; p++) s += g_part[p * (B_ * L_) + b * L_ + l];
        v[i] = s;
    }
    float mx = fmaxf(fmaxf(v[0], v[1]), fmaxf(v[2], v[3]));
    #pragma unroll
    for (int off = 16; off; off >>= 1) mx = fmaxf(mx, __shfl_xor_sync(0xffffffffu, mx, off));
    if ((tid & 31) == 0) red[tid >> 5] = mx;
    __syncthreads();
    float bm = red[0];
    #pragma unroll
    for (int i = 1; i < 8; i++) bm = fmaxf(bm, red[i]);
    __syncthreads();
    float sum = 0.f;
    #pragma unroll
    for (int i = 0; i < 4; i++) { v[i] = expf(v[i] - bm); sum += v[i]; }
    #pragma unroll
    for (int off = 16; off; off >>= 1) sum += __shfl_xor_sync(0xffffffffu, sum, off);
    if ((tid & 31) == 0) red[tid >> 5] = sum;
    __syncthreads();
    float tot = 0.f;
    #pragma unroll
    for (int i = 0; i < 8; i++) tot += red[i];
    float inv = 1.f / tot;
    #pragma unroll
    for (int i = 0; i < 4; i++) out_att[b * L_ + tid + i * 256] = v[i] * inv;
}

// ============================================================
// context partials, float4 over ENC, L split 4 ways
// grid(2, B_, 4), block(256)
// ============================================================
__global__ __launch_bounds__(256) void k_context(const float* __restrict__ enc,
                                                 const float* __restrict__ att) {
    const int b = blockIdx.y, z = blockIdx.z, tid = threadIdx.x;
    const int e4 = blockIdx.x * 256 + tid;
    __shared__ float sa[256];
    sa[tid] = att[b * L_ + z * 256 + tid];
    __syncthreads();

    const float4* ep = (const float4*)(enc + (size_t)b * L_ * ENC_ + (size_t)z * 256 * ENC_) + e4;
    float4 acc = make_float4(0.f, 0.f, 0.f, 0.f);
    #pragma unroll 8
    for (int l = 0; l < 256; l++) {
        float4 x = ep[(size_t)l * (ENC_ / 4)];
        float w = sa[l];
        acc.x = fmaf(w, x.x, acc.x);
        acc.y = fmaf(w, x.y, acc.y);
        acc.z = fmaf(w, x.z, acc.z);
        acc.w = fmaf(w, x.w, acc.w);
    }
    ((float4*)(g_ctxp + (size_t)z * B_ * ENC_ + (size_t)b * ENC_))[e4] = acc;
}

__global__ void k_ctx_reduce(float* __restrict__ ctx) {
    int i = blockIdx.x * 256 + threadIdx.x;
    float s = 0.f;
    #pragma unroll
    for (int z = 0; z < 4; z++) s += g_ctxp[z * (B_ * ENC_) + i];
    ctx[i] = s;
}

// ============================================================
extern "C" void kernel_launch(void* const* d_in, const int* in_sizes, int n_in,
                              void* d_out, int out_size) {
    const float* enc  = (const float*)d_in[0];
    const float* dech = (const float*)d_in[1];
    const float* We   = (const float*)d_in[2];
    const float* be   = (const float*)d_in[3];
    const float* Wd   = (const float*)d_in[4];
    const float* bd   = (const float*)d_in[5];
    const float* Wf   = (const float*)d_in[6];
    // d_in[7] = b_full: constant logit shift, invariant under softmax -> unused

    float* out_ctx = (float*)d_out;
    float* out_att = (float*)d_out + B_ * ENC_;

    static int smem_set = 0;
    if (!smem_set) {
        cudaFuncSetAttribute(k_logits_mma, cudaFuncAttributeMaxDynamicSharedMemorySize, SMEM_DYN);
        smem_set = 1;
    }

    dim3 gt(ENC_ / 32, ATT_ / 32);
    k_transpose<<<gt, dim3(32, 8)>>>(We);
    k_att2<<<B_, 512>>>(dech, Wd, bd, be);
    dim3 g2(4, B_ * L_ / 128);                   // (4, 512)
    k_logits_mma<<<g2, 256, SMEM_DYN>>>(enc, Wf);
    k_softmax<<<B_, 256>>>(out_att);
    dim3 g4(2, B_, 4);
    k_context<<<g4, 256>>>(enc, out_att);
    k_ctx_reduce<<<B_ * ENC_ / 256, 256>>>(out_ctx);
}